// round 6
// baseline (speedup 1.0000x reference)
#include <cuda_runtime.h>
#include <cuda_bf16.h>

// Shapes fixed by the problem definition.
#define BATCH    256
#define HWPIX    1024           // 32*32
#define CHAN     256
#define NPART    4
#define PSIZE    64             // BATCH / NPART
#define EPSV     0.001f
#define NUNITS   4096           // BATCH * 16 chunks of 64 pixels
#define UNIT_PIX 64
#define GRID     512            // NUNITS / GRID = 8 units per CTA, exact
#define UPC      8              // units per CTA

// Scratch (allocation-free rule): device globals. g_sum/g_sq are zero at
// module load and re-zeroed by the last-arriving CTA every run -> every
// graph replay sees identical state (deterministic).
__device__ float    g_sum[NPART][CHAN];
__device__ float    g_sq [NPART][CHAN];
__device__ unsigned g_cnt1;   // barrier-1 arrival counter (reset by last arriver)
__device__ unsigned g_rel1;   // barrier-1 release epoch (monotonic across replays)
__device__ unsigned g_cnt2;   // stats-consumed counter (reset by last arriver)

// ---------------------------------------------------------------------------
// One persistent kernel: stats -> grid barrier -> normalize.
// grid = 512 CTAs, __launch_bounds__(256,4) on a 152-SM part -> max resident
// 608 >= 512, so all CTAs co-resident: software grid barrier is deadlock-free.
// Every CTA owns exactly 8 units in both phases (perfect balance, no
// straggler stall at the barrier). Phase 2 walks its units in REVERSE so the
// most recently read x lines (still L2-resident) are consumed first, and
// output uses streaming stores so it doesn't evict that x window.
// ---------------------------------------------------------------------------
__global__ void __launch_bounds__(256, 4)
k_fused(const float4* __restrict__ x, float4* __restrict__ out,
        const float* __restrict__ gamma, const float* __restrict__ beta,
        const int* __restrict__ perm) {
    const int      t    = threadIdx.x;
    const int      c4   = t & 63;
    const int      psub = t >> 6;
    const unsigned bid  = blockIdx.x;

    __shared__ int   spart[BATCH];     // partition of each batch index
    __shared__ float ssum[4][CHAN];
    __shared__ float ssq [4][CHAN];
    __shared__ float sscale[NPART][CHAN];
    __shared__ float sbias [NPART][CHAN];
    __shared__ int   s_last;

    // Build partition map per-CTA: position of b in perm, / 64.
    spart[perm[t]] = t >> 6;           // t / PSIZE
    __syncthreads();

    // ---------------- Phase 1: stats (forward unit order) ----------------
    #pragma unroll
    for (int k = 0; k < UPC; k++) {
        const unsigned u = bid + (unsigned)k * GRID;
        const int b     = (int)(u >> 4);
        const int chunk = (int)(u & 15);
        const float4* base =
            x + ((size_t)b * HWPIX + (size_t)chunk * UNIT_PIX) * (CHAN / 4) + c4;

        float4 s = make_float4(0.f, 0.f, 0.f, 0.f);
        float4 q = make_float4(0.f, 0.f, 0.f, 0.f);
        #pragma unroll
        for (int i = 0; i < 16; i++) {
            float4 v = base[(size_t)(i * 4 + psub) * (CHAN / 4)];
            s.x += v.x; s.y += v.y; s.z += v.z; s.w += v.w;
            q.x += v.x * v.x; q.y += v.y * v.y; q.z += v.z * v.z; q.w += v.w * v.w;
        }

        __syncthreads();               // protect smem reuse from previous unit
        const int cbase = c4 * 4;
        ssum[psub][cbase + 0] = s.x; ssum[psub][cbase + 1] = s.y;
        ssum[psub][cbase + 2] = s.z; ssum[psub][cbase + 3] = s.w;
        ssq[psub][cbase + 0]  = q.x; ssq[psub][cbase + 1]  = q.y;
        ssq[psub][cbase + 2]  = q.z; ssq[psub][cbase + 3]  = q.w;
        __syncthreads();

        const int p = spart[b];
        atomicAdd(&g_sum[p][t], ssum[0][t] + ssum[1][t] + ssum[2][t] + ssum[3][t]);
        atomicAdd(&g_sq[p][t],  ssq[0][t]  + ssq[1][t]  + ssq[2][t]  + ssq[3][t]);
    }

    // ---------------- Grid barrier (all atomics visible) -----------------
    __syncthreads();
    if (t == 0) {
        __threadfence();
        unsigned r0  = atomicAdd(&g_rel1, 0u);        // epoch before arriving
        unsigned old = atomicAdd(&g_cnt1, 1u);
        if (old == GRID - 1u) {
            atomicExch(&g_cnt1, 0u);                  // reset for next replay
            __threadfence();
            atomicAdd(&g_rel1, 1u);                   // release everyone
        } else {
            while (atomicAdd(&g_rel1, 0u) == r0) { __nanosleep(64); }
        }
        __threadfence();
    }
    __syncthreads();

    // -------- Fold stats into fused scale/bias in shared (once/CTA) ------
    {
        const float invN = 1.0f / (float)(PSIZE * HWPIX);
        const float* sm = &g_sum[0][0];
        const float* sq = &g_sq[0][0];
        float* sc = &sscale[0][0];
        float* sb = &sbias[0][0];
        #pragma unroll
        for (int i = t; i < NPART * CHAN; i += 256) {
            float mean = sm[i] * invN;
            float var  = sq[i] * invN - mean * mean;
            float s    = gamma[i] * rsqrtf(var + EPSV);
            sc[i] = s;
            sb[i] = beta[i] - mean * s;
        }
        __syncthreads();
        // Last CTA to consume the accumulators re-zeroes them for the next
        // replay (no CTA reads g_sum/g_sq after this point).
        if (t == 0) s_last = (atomicAdd(&g_cnt2, 1u) == GRID - 1u) ? 1 : 0;
        __syncthreads();
        if (s_last) {
            float* gs = &g_sum[0][0];
            float* gq = &g_sq[0][0];
            #pragma unroll
            for (int i = t; i < NPART * CHAN; i += 256) { gs[i] = 0.f; gq[i] = 0.f; }
            __threadfence();
            if (t == 0) atomicExch(&g_cnt2, 0u);
        }
    }

    // ---------------- Phase 2: normalize (REVERSE unit order) ------------
    #pragma unroll
    for (int k = UPC - 1; k >= 0; k--) {
        const unsigned u = bid + (unsigned)k * GRID;
        const int b     = (int)(u >> 4);
        const int chunk = (int)(u & 15);
        const int p     = spart[b];

        const float4 sc = *(const float4*)&sscale[p][c4 * 4];
        const float4 bi = *(const float4*)&sbias[p][c4 * 4];

        const size_t base =
            ((size_t)b * HWPIX + (size_t)chunk * UNIT_PIX) * (CHAN / 4) + c4;
        #pragma unroll
        for (int i = 0; i < 16; i++) {
            size_t idx = base + (size_t)(i * 4 + psub) * (CHAN / 4);
            float4 v = x[idx];
            v.x = v.x * sc.x + bi.x;
            v.y = v.y * sc.y + bi.y;
            v.z = v.z * sc.z + bi.z;
            v.w = v.w * sc.w + bi.w;
            __stcs(&out[idx], v);      // streaming store: don't evict x from L2
        }
    }
}

// ---------------------------------------------------------------------------
extern "C" void kernel_launch(void* const* d_in, const int* in_sizes, int n_in,
                              void* d_out, int out_size) {
    const float* x     = (const float*)d_in[0];
    const float* gamma = (const float*)d_in[1];
    const float* beta  = (const float*)d_in[2];
    const int*   perm  = (const int*)d_in[3];

    k_fused<<<GRID, 256>>>((const float4*)x, (float4*)d_out, gamma, beta, perm);
}

// round 7
// speedup vs baseline: 1.0511x; 1.0511x over previous
#include <cuda_runtime.h>
#include <cuda_bf16.h>

// Shapes fixed by the problem definition.
#define BATCH    256
#define HWPIX    1024           // 32*32
#define CHAN     256
#define NPART    4
#define PSIZE    64             // BATCH / NPART
#define EPSV     0.001f
#define NUNITS   4096u          // BATCH * 16 chunks of 64 pixels
#define UNIT_PIX 64

// Scratch (allocation-free rule): device globals. All counters/accumulators
// are returned to zero by in-kernel handshakes before the kernel retires ->
// every graph replay sees identical initial state (deterministic).
__device__ float    g_sum[NPART][CHAN];
__device__ float    g_sq [NPART][CHAN];
__device__ unsigned g_tk1;    // phase-1 ticket   (reset by barrier master)
__device__ unsigned g_tk2;    // phase-2 ticket   (reset by last finisher)
__device__ unsigned g_cnt1;   // barrier arrivals (reset by barrier master)
__device__ unsigned g_rel1;   // barrier release epoch (monotonic)
__device__ unsigned g_fc;     // fold-consumed counter (reset by its last)
__device__ unsigned g_done;   // phase-2 finishers (reset by last finisher)

// ---------------------------------------------------------------------------
// One persistent kernel: stats -> grid barrier -> fold -> normalize.
// grid = 4 * num_SMs, __launch_bounds__(256,4) => all CTAs resident, so the
// software grid barrier is deadlock-free. BOTH phases pull 64-pixel units
// from a global atomic ticket: perfect load balance (+-1 unit) independent of
// per-SM speed spread, mimicking the HW wave scheduler that gave the
// standalone kernels their 80% DRAM. Phase 2 consumes tickets in REVERSE
// global order to hit the L2-resident x tail from phase 1.
// ---------------------------------------------------------------------------
__global__ void __launch_bounds__(256, 4)
k_fused(const float4* __restrict__ x, float4* __restrict__ out,
        const float* __restrict__ gamma, const float* __restrict__ beta,
        const int* __restrict__ perm) {
    const int      t    = threadIdx.x;
    const int      c4   = t & 63;
    const int      psub = t >> 6;
    const unsigned nCTA = gridDim.x;

    __shared__ int      spart[BATCH];    // partition of each batch index
    __shared__ float    ssum[4][CHAN];
    __shared__ float    ssq [4][CHAN];
    __shared__ float    sscale[NPART][CHAN];
    __shared__ float    sbias [NPART][CHAN];
    __shared__ unsigned stk[2];          // double-buffered ticket broadcast
    __shared__ int      slast;

    // Build partition map per-CTA: position of b in perm, / 64.
    spart[perm[t]] = t >> 6;             // t / PSIZE
    // (published by the first __syncthreads in the loop below)

    // ---------------- Phase 1: stats (dynamic tickets, forward) ----------
    for (unsigned it = 0; ; it++) {
        if (t == 0) stk[it & 1u] = atomicAdd(&g_tk1, 1u);
        __syncthreads();                 // publish ticket (and spart on it=0)
        const unsigned u = stk[it & 1u];
        if (u >= NUNITS) break;

        const int b     = (int)(u >> 4);
        const int chunk = (int)(u & 15);
        const float4* base =
            x + ((size_t)b * HWPIX + (size_t)chunk * UNIT_PIX) * (CHAN / 4) + c4;

        float4 s = make_float4(0.f, 0.f, 0.f, 0.f);
        float4 q = make_float4(0.f, 0.f, 0.f, 0.f);
        #pragma unroll
        for (int i = 0; i < 16; i++) {
            float4 v = base[(size_t)(i * 4 + psub) * (CHAN / 4)];
            s.x += v.x; s.y += v.y; s.z += v.z; s.w += v.w;
            q.x += v.x * v.x; q.y += v.y * v.y; q.z += v.z * v.z; q.w += v.w * v.w;
        }

        const int cbase = c4 * 4;
        ssum[psub][cbase + 0] = s.x; ssum[psub][cbase + 1] = s.y;
        ssum[psub][cbase + 2] = s.z; ssum[psub][cbase + 3] = s.w;
        ssq[psub][cbase + 0]  = q.x; ssq[psub][cbase + 1]  = q.y;
        ssq[psub][cbase + 2]  = q.z; ssq[psub][cbase + 3]  = q.w;
        __syncthreads();

        const int p = spart[b];
        atomicAdd(&g_sum[p][t], ssum[0][t] + ssum[1][t] + ssum[2][t] + ssum[3][t]);
        atomicAdd(&g_sq[p][t],  ssq[0][t]  + ssq[1][t]  + ssq[2][t]  + ssq[3][t]);
        // (ssum reads are ordered before the next iteration's writes by the
        //  ticket-publish __syncthreads at the top of the loop)
    }

    // ---------------- Grid barrier (all atomics visible) -----------------
    __syncthreads();
    if (t == 0) {
        __threadfence();
        unsigned r0  = atomicAdd(&g_rel1, 0u);        // epoch before arriving
        unsigned old = atomicAdd(&g_cnt1, 1u);
        if (old == nCTA - 1u) {                       // master: everyone done
            atomicExch(&g_cnt1, 0u);                  // reset for next replay
            atomicExch(&g_tk1, 0u);                   // no more phase-1 grabs
            __threadfence();
            atomicAdd(&g_rel1, 1u);                   // release
        } else {
            while (atomicAdd(&g_rel1, 0u) == r0) { __nanosleep(64); }
        }
        __threadfence();
    }
    __syncthreads();

    // -------- Fold stats into fused scale/bias in shared (once/CTA) ------
    {
        const float invN = 1.0f / (float)(PSIZE * HWPIX);
        const float* sm = &g_sum[0][0];
        const float* sq = &g_sq[0][0];
        float* sc = &sscale[0][0];
        float* sb = &sbias[0][0];
        #pragma unroll
        for (int i = t; i < NPART * CHAN; i += 256) {
            float mean = sm[i] * invN;
            float var  = sq[i] * invN - mean * mean;
            float s    = gamma[i] * rsqrtf(var + EPSV);
            sc[i] = s;
            sb[i] = beta[i] - mean * s;
        }
        __syncthreads();
        // Last CTA to consume the accumulators re-zeroes them (R6-proven).
        if (t == 0) slast = (atomicAdd(&g_fc, 1u) == nCTA - 1u) ? 1 : 0;
        __syncthreads();
        if (slast) {
            float* gs = &g_sum[0][0];
            float* gq = &g_sq[0][0];
            #pragma unroll
            for (int i = t; i < NPART * CHAN; i += 256) { gs[i] = 0.f; gq[i] = 0.f; }
            __threadfence();
            if (t == 0) atomicExch(&g_fc, 0u);
        }
    }

    // ---------------- Phase 2: normalize (dynamic tickets, REVERSED) -----
    for (unsigned it = 0; ; it++) {
        if (t == 0) stk[it & 1u] = atomicAdd(&g_tk2, 1u);
        __syncthreads();
        const unsigned tk = stk[it & 1u];
        if (tk >= NUNITS) break;
        const unsigned u = NUNITS - 1u - tk;          // newest-read units first

        const int b     = (int)(u >> 4);
        const int chunk = (int)(u & 15);
        const int p     = spart[b];

        const float4 sc = *(const float4*)&sscale[p][c4 * 4];
        const float4 bi = *(const float4*)&sbias[p][c4 * 4];

        const size_t base =
            ((size_t)b * HWPIX + (size_t)chunk * UNIT_PIX) * (CHAN / 4) + c4;
        #pragma unroll
        for (int i = 0; i < 16; i++) {
            size_t idx = base + (size_t)(i * 4 + psub) * (CHAN / 4);
            float4 v = x[idx];
            v.x = v.x * sc.x + bi.x;
            v.y = v.y * sc.y + bi.y;
            v.z = v.z * sc.z + bi.z;
            v.w = v.w * sc.w + bi.w;
            out[idx] = v;
        }
    }

    // ---------------- Exit handshake: reset tickets for next replay ------
    __syncthreads();
    if (t == 0) slast = (atomicAdd(&g_done, 1u) == nCTA - 1u) ? 1 : 0;
    __syncthreads();
    if (slast && t == 0) {
        atomicExch(&g_tk2, 0u);
        __threadfence();
        atomicExch(&g_done, 0u);
    }
}

// ---------------------------------------------------------------------------
extern "C" void kernel_launch(void* const* d_in, const int* in_sizes, int n_in,
                              void* d_out, int out_size) {
    const float* x     = (const float*)d_in[0];
    const float* gamma = (const float*)d_in[1];
    const float* beta  = (const float*)d_in[2];
    const int*   perm  = (const int*)d_in[3];

    int nsm = 0;
    cudaDeviceGetAttribute(&nsm, cudaDevAttrMultiProcessorCount, 0);
    if (nsm <= 0) nsm = 148;                 // defensive fallback
    const int grid = 4 * nsm;                // __launch_bounds__(256,4) => resident

    k_fused<<<grid, 256>>>((const float4*)x, (float4*)d_out, gamma, beta, perm);
}